// round 2
// baseline (speedup 1.0000x reference)
#include <cuda_runtime.h>

// ---------------------------------------------------------------------------
// MultiHeadAttention  (B=4, S=2048, E=1024, H=16, hd=64), fp32 end-to-end.
// Stage 1: QKV = x @ W_attn + b_attn          [8192,1024]x[1024,3072]
// Stage 2: causal flash attention per (b,h)   64x64 tiles, online softmax
// Stage 3: out = attn @ W_proj + b_proj       [8192,1024]x[1024,1024]
// All FMA work uses packed fma.rn.f32x2 (FFMA2) for 2x fp32 throughput.
// ---------------------------------------------------------------------------

#define C_S   2048
#define C_E   1024
#define C_3E  3072
#define C_H   16
#define C_TOK 8192   // B*S

typedef unsigned long long ull;

__device__ __forceinline__ ull pk2(float lo, float hi) {
    ull r; asm("mov.b64 %0,{%1,%2};" : "=l"(r) : "f"(lo), "f"(hi)); return r;
}
__device__ __forceinline__ ull dup2(float v) {
    ull r; asm("mov.b64 %0,{%1,%1};" : "=l"(r) : "f"(v)); return r;
}
__device__ __forceinline__ void fma2(ull& d, ull a, ull b) {
    asm("fma.rn.f32x2 %0, %1, %2, %0;" : "+l"(d) : "l"(a), "l"(b));
}
__device__ __forceinline__ ull mul2(ull a, ull b) {
    ull r; asm("mul.rn.f32x2 %0, %1, %2;" : "=l"(r) : "l"(a), "l"(b)); return r;
}
__device__ __forceinline__ float2 upk2(ull v) {
    float2 f; asm("mov.b64 {%0,%1}, %2;" : "=f"(f.x), "=f"(f.y) : "l"(v)); return f;
}

// Scratch (allocation-free rule: __device__ globals)
__device__ float g_qkv[(size_t)C_TOK * C_3E];   // [token, 3E]
__device__ float g_att[(size_t)C_TOK * C_E];    // [token, E] = [b,s,h*64+d]

// ---------------------------------------------------------------------------
// SGEMM + bias: C[M,N] = A[M,K] @ B[K,N] + bias[N]. Row-major, all dims
// multiples of tile sizes (M%128==0, N%128==0, K%16==0).
// 128x128x16 tiles, 256 threads, 8x8 per thread via f32x2 accumulators,
// double-buffered smem (1 sync per K-tile).
// ---------------------------------------------------------------------------
__global__ __launch_bounds__(256, 2)
void sgemm_bias_kernel(const float* __restrict__ A, const float* __restrict__ B,
                       const float* __restrict__ bias, float* __restrict__ C,
                       int M, int N, int K)
{
    __shared__ float As[2][16][128 + 4];
    __shared__ float Bs[2][16][128];

    const int tid = threadIdx.x;
    const int tx = tid & 15;        // col group (8 cols)
    const int ty = tid >> 4;        // row group (8 rows)
    const int bm = blockIdx.y * 128;
    const int bn = blockIdx.x * 128;

    // A loads: 2x float4 per thread per tile
    const int arow = tid >> 2;      // 0..63 (and +64)
    const int akq  = tid & 3;       // k-quad
    // B loads: 2x float4 per thread per tile
    const int bkr = tid >> 5;       // 0..7 (and +8)
    const int bc4 = tid & 31;       // col quad

    const float* Aptr = A + (size_t)(bm + arow) * K + akq * 4;
    const float* Bptr = B + (size_t)bkr * N + bn + bc4 * 4;

    ull acc[8][4];
    #pragma unroll
    for (int i = 0; i < 8; i++)
        #pragma unroll
        for (int j = 0; j < 4; j++) acc[i][j] = 0ull;

    float4 pa0, pa1, pb0, pb1;
    // prologue: tile 0
    pa0 = *(const float4*)(Aptr);
    pa1 = *(const float4*)(Aptr + (size_t)64 * K);
    pb0 = *(const float4*)(Bptr);
    pb1 = *(const float4*)(Bptr + (size_t)8 * N);
    {
        As[0][akq * 4 + 0][arow] = pa0.x;
        As[0][akq * 4 + 1][arow] = pa0.y;
        As[0][akq * 4 + 2][arow] = pa0.z;
        As[0][akq * 4 + 3][arow] = pa0.w;
        As[0][akq * 4 + 0][arow + 64] = pa1.x;
        As[0][akq * 4 + 1][arow + 64] = pa1.y;
        As[0][akq * 4 + 2][arow + 64] = pa1.z;
        As[0][akq * 4 + 3][arow + 64] = pa1.w;
        *(float4*)&Bs[0][bkr][bc4 * 4]     = pb0;
        *(float4*)&Bs[0][bkr + 8][bc4 * 4] = pb1;
    }
    __syncthreads();

    const int nt = K / 16;
    for (int t = 0; t < nt; t++) {
        const int cur = t & 1;
        if (t + 1 < nt) {
            const float* Ap = Aptr + (size_t)(t + 1) * 16;
            pa0 = *(const float4*)(Ap);
            pa1 = *(const float4*)(Ap + (size_t)64 * K);
            const float* Bp = Bptr + (size_t)(t + 1) * 16 * N;
            pb0 = *(const float4*)(Bp);
            pb1 = *(const float4*)(Bp + (size_t)8 * N);
        }
        #pragma unroll
        for (int k = 0; k < 16; k++) {
            const float4 a0 = *(const float4*)&As[cur][k][ty * 8];
            const float4 a1 = *(const float4*)&As[cur][k][ty * 8 + 4];
            const float4 b0 = *(const float4*)&Bs[cur][k][tx * 8];
            const float4 b1 = *(const float4*)&Bs[cur][k][tx * 8 + 4];
            const ull bv0 = pk2(b0.x, b0.y);
            const ull bv1 = pk2(b0.z, b0.w);
            const ull bv2 = pk2(b1.x, b1.y);
            const ull bv3 = pk2(b1.z, b1.w);
            const float av[8] = { a0.x, a0.y, a0.z, a0.w, a1.x, a1.y, a1.z, a1.w };
            #pragma unroll
            for (int i = 0; i < 8; i++) {
                const ull ad = dup2(av[i]);
                fma2(acc[i][0], ad, bv0);
                fma2(acc[i][1], ad, bv1);
                fma2(acc[i][2], ad, bv2);
                fma2(acc[i][3], ad, bv3);
            }
        }
        if (t + 1 < nt) {
            const int nxt = cur ^ 1;
            As[nxt][akq * 4 + 0][arow] = pa0.x;
            As[nxt][akq * 4 + 1][arow] = pa0.y;
            As[nxt][akq * 4 + 2][arow] = pa0.z;
            As[nxt][akq * 4 + 3][arow] = pa0.w;
            As[nxt][akq * 4 + 0][arow + 64] = pa1.x;
            As[nxt][akq * 4 + 1][arow + 64] = pa1.y;
            As[nxt][akq * 4 + 2][arow + 64] = pa1.z;
            As[nxt][akq * 4 + 3][arow + 64] = pa1.w;
            *(float4*)&Bs[nxt][bkr][bc4 * 4]     = pb0;
            *(float4*)&Bs[nxt][bkr + 8][bc4 * 4] = pb1;
        }
        __syncthreads();
    }

    // epilogue: add bias, store
    const float4 bb0 = *(const float4*)&bias[bn + tx * 8];
    const float4 bb1 = *(const float4*)&bias[bn + tx * 8 + 4];
    #pragma unroll
    for (int i = 0; i < 8; i++) {
        const int row = bm + ty * 8 + i;
        float* cp = C + (size_t)row * N + bn + tx * 8;
        const float2 c0 = upk2(acc[i][0]);
        const float2 c1 = upk2(acc[i][1]);
        const float2 c2 = upk2(acc[i][2]);
        const float2 c3 = upk2(acc[i][3]);
        float4 o0 = make_float4(c0.x + bb0.x, c0.y + bb0.y, c1.x + bb0.z, c1.y + bb0.w);
        float4 o1 = make_float4(c2.x + bb1.x, c2.y + bb1.y, c3.x + bb1.z, c3.y + bb1.w);
        *(float4*)(cp)     = o0;
        *(float4*)(cp + 4) = o1;
    }
}

// ---------------------------------------------------------------------------
// Flash attention, fp32, causal. Grid: (32 q-tiles [reversed for balance],
// 64 = B*H). Block: 256 threads as 16x16 grid, 4x4 microtiles over 64x64.
// smem: Qt = Q^T [d][row], KP = K^T [d][col] then P^T [j][row,xor-swizzled],
// Vs = V [j][d]. Exactly 48KB static.
// ---------------------------------------------------------------------------
__global__ __launch_bounds__(256, 2)
void flash_attn_kernel(const float* __restrict__ qkv, float* __restrict__ outp)
{
    __shared__ float Qt[64 * 64];
    __shared__ float KP[64 * 64];
    __shared__ float Vs[64 * 64];

    const int qt  = (int)gridDim.x - 1 - (int)blockIdx.x;   // heavy tiles first
    const int bh  = blockIdx.y;
    const int b   = bh >> 4;
    const int h   = bh & 15;
    const int tid = threadIdx.x;
    const int tx  = tid & 15;   // col group (4 cols / d group)
    const int ty  = tid >> 4;   // row group (4 rows)

    const float* Qg = qkv + (size_t)b * C_S * C_3E + h * 64;
    const float* Kg = Qg + C_E;
    const float* Vg = Qg + 2 * C_E;

    // Load Q^T: Qt[d][r]
    #pragma unroll
    for (int it = 0; it < 4; it++) {
        const int lid = it * 256 + tid;
        const int r  = lid & 63;
        const int d4 = lid >> 6;
        const float4 v = *(const float4*)(Qg + (size_t)(qt * 64 + r) * C_3E + d4 * 4);
        Qt[(d4 * 4 + 0) * 64 + r] = v.x;
        Qt[(d4 * 4 + 1) * 64 + r] = v.y;
        Qt[(d4 * 4 + 2) * 64 + r] = v.z;
        Qt[(d4 * 4 + 3) * 64 + r] = v.w;
    }

    const float NEG_INF = __int_as_float(0xff800000);
    float m[4], l[4];
    ull o2[4][2];
    #pragma unroll
    for (int r = 0; r < 4; r++) { m[r] = NEG_INF; l[r] = 0.f; o2[r][0] = 0ull; o2[r][1] = 0ull; }

    for (int kt = 0; kt <= qt; kt++) {
        __syncthreads();   // prior PV reads of KP/Vs done (also covers Q load on kt==0)

        // Load K^T into KP: KP[d][c]
        #pragma unroll
        for (int it = 0; it < 4; it++) {
            const int lid = it * 256 + tid;
            const int c  = lid & 63;
            const int d4 = lid >> 6;
            const float4 v = *(const float4*)(Kg + (size_t)(kt * 64 + c) * C_3E + d4 * 4);
            KP[(d4 * 4 + 0) * 64 + c] = v.x;
            KP[(d4 * 4 + 1) * 64 + c] = v.y;
            KP[(d4 * 4 + 2) * 64 + c] = v.z;
            KP[(d4 * 4 + 3) * 64 + c] = v.w;
        }
        // Load V natural: Vs[j][d] (coalesced)
        #pragma unroll
        for (int it = 0; it < 4; it++) {
            const int lid = it * 256 + tid;
            const int jr = lid >> 4;
            const int d4 = lid & 15;
            *(float4*)(Vs + jr * 64 + d4 * 4) =
                *(const float4*)(Vg + (size_t)(kt * 64 + jr) * C_3E + d4 * 4);
        }
        __syncthreads();

        // --- QK^T: S tile, 4x4 microtile per thread, f32x2 packed over cols
        ull s2[4][2];
        #pragma unroll
        for (int r = 0; r < 4; r++) { s2[r][0] = 0ull; s2[r][1] = 0ull; }
        #pragma unroll 16
        for (int d = 0; d < 64; d++) {
            const float4 a  = *(const float4*)(Qt + d * 64 + ty * 4);
            const float4 bk = *(const float4*)(KP + d * 64 + tx * 4);
            const ull b01 = pk2(bk.x, bk.y);
            const ull b23 = pk2(bk.z, bk.w);
            const ull a0 = dup2(a.x), a1 = dup2(a.y), a2 = dup2(a.z), a3 = dup2(a.w);
            fma2(s2[0][0], a0, b01); fma2(s2[0][1], a0, b23);
            fma2(s2[1][0], a1, b01); fma2(s2[1][1], a1, b23);
            fma2(s2[2][0], a2, b01); fma2(s2[2][1], a2, b23);
            fma2(s2[3][0], a3, b01); fma2(s2[3][1], a3, b23);
        }

        // --- online softmax (row stats across the 16 tx-threads of each row)
        float p[4][4];
        float alpha[4];
        const bool diag = (kt == qt);
        #pragma unroll
        for (int r = 0; r < 4; r++) {
            const float2 t0 = upk2(s2[r][0]);
            const float2 t1 = upk2(s2[r][1]);
            float sv[4] = { t0.x, t0.y, t1.x, t1.y };
            float mx = NEG_INF;
            #pragma unroll
            for (int c = 0; c < 4; c++) {
                float xv = sv[c] * 0.125f;            // 1/sqrt(64)
                if (diag && (tx * 4 + c > ty * 4 + r)) xv = -1e30f;
                sv[c] = xv;
                mx = fmaxf(mx, xv);
            }
            mx = fmaxf(mx, __shfl_xor_sync(0xffffffffu, mx, 1));
            mx = fmaxf(mx, __shfl_xor_sync(0xffffffffu, mx, 2));
            mx = fmaxf(mx, __shfl_xor_sync(0xffffffffu, mx, 4));
            mx = fmaxf(mx, __shfl_xor_sync(0xffffffffu, mx, 8));
            const float mn = fmaxf(m[r], mx);
            alpha[r] = __expf(m[r] - mn);
            m[r] = mn;
            float ls = 0.f;
            #pragma unroll
            for (int c = 0; c < 4; c++) {
                const float pe = __expf(sv[c] - mn);
                p[r][c] = pe;
                ls += pe;
            }
            ls += __shfl_xor_sync(0xffffffffu, ls, 1);
            ls += __shfl_xor_sync(0xffffffffu, ls, 2);
            ls += __shfl_xor_sync(0xffffffffu, ls, 4);
            ls += __shfl_xor_sync(0xffffffffu, ls, 8);
            l[r] = l[r] * alpha[r] + ls;
        }

        __syncthreads();   // all QK reads of KP done before overwrite with P^T
        // Store P^T (xor-swizzled row groups for conflict-free access)
        #pragma unroll
        for (int c = 0; c < 4; c++) {
            const float4 pv = make_float4(p[0][c], p[1][c], p[2][c], p[3][c]);
            *(float4*)(KP + (tx * 4 + c) * 64 + ((ty ^ tx) * 4)) = pv;
        }
        __syncthreads();   // P^T visible

        // rescale O by alpha
        #pragma unroll
        for (int r = 0; r < 4; r++) {
            const ull a2 = dup2(alpha[r]);
            o2[r][0] = mul2(o2[r][0], a2);
            o2[r][1] = mul2(o2[r][1], a2);
        }
        // --- P @ V
        #pragma unroll 8
        for (int j = 0; j < 64; j++) {
            const float4 a = *(const float4*)(KP + j * 64 + ((ty ^ (j >> 2)) * 4));
            const float4 v = *(const float4*)(Vs + j * 64 + tx * 4);
            const ull v01 = pk2(v.x, v.y);
            const ull v23 = pk2(v.z, v.w);
            const ull a0 = dup2(a.x), a1 = dup2(a.y), a2r = dup2(a.z), a3 = dup2(a.w);
            fma2(o2[0][0], a0,  v01); fma2(o2[0][1], a0,  v23);
            fma2(o2[1][0], a1,  v01); fma2(o2[1][1], a1,  v23);
            fma2(o2[2][0], a2r, v01); fma2(o2[2][1], a2r, v23);
            fma2(o2[3][0], a3,  v01); fma2(o2[3][1], a3,  v23);
        }
    }

    // epilogue: divide by l, store [token, h*64+d]
    float* Og = outp + ((size_t)(b * C_S + qt * 64)) * C_E + h * 64;
    #pragma unroll
    for (int r = 0; r < 4; r++) {
        const float inv = 1.0f / l[r];
        const float2 c0 = upk2(o2[r][0]);
        const float2 c1 = upk2(o2[r][1]);
        const float4 o = make_float4(c0.x * inv, c0.y * inv, c1.x * inv, c1.y * inv);
        *(float4*)(Og + (size_t)(ty * 4 + r) * C_E + tx * 4) = o;
    }
}

// ---------------------------------------------------------------------------
extern "C" void kernel_launch(void* const* d_in, const int* in_sizes, int n_in,
                              void* d_out, int out_size)
{
    (void)in_sizes; (void)n_in; (void)out_size;
    const float* x  = (const float*)d_in[0];
    const float* Wa = (const float*)d_in[1];
    const float* ba = (const float*)d_in[2];
    const float* Wp = (const float*)d_in[3];
    const float* bp = (const float*)d_in[4];
    float* out = (float*)d_out;

    float *qkv = nullptr, *att = nullptr;
    cudaGetSymbolAddress((void**)&qkv, g_qkv);
    cudaGetSymbolAddress((void**)&att, g_att);

    // Stage 1: QKV projection
    sgemm_bias_kernel<<<dim3(C_3E / 128, C_TOK / 128), 256>>>(x, Wa, ba, qkv,
                                                              C_TOK, C_3E, C_E);
    // Stage 2: causal flash attention
    flash_attn_kernel<<<dim3(C_S / 64, 4 * C_H), 256>>>(qkv, att);
    // Stage 3: output projection
    sgemm_bias_kernel<<<dim3(C_E / 128, C_TOK / 128), 256>>>(att, Wp, bp, out,
                                                             C_TOK, C_E, C_E);
}

// round 5
// speedup vs baseline: 1.2148x; 1.2148x over previous
#include <cuda_runtime.h>
#include <cuda_bf16.h>
#include <cstdint>

// ---------------------------------------------------------------------------
// MultiHeadAttention (B=4, S=2048, E=1024, H=16, hd=64), fp32 in/out.
// GEMMs on legacy tensor path: mma.sync.m16n8k16 bf16 with 3-term split
// packed along K (K'=3072): A3=[ah|ah|al], B3=[bh|bl|bh]  =>  fp32-accurate.
// Flash attention stays on FFMA2 (f32x2); its epilogue emits packed A3.
// ---------------------------------------------------------------------------

#define C_S   2048
#define C_E   1024
#define C_3E  3072
#define C_H   16
#define C_TOK 8192
#define K3    3072      // packed K for both GEMM stages
#define KC    32        // bf16 K-chunk per pipeline stage
#define NCH   (K3/KC)   // 96

typedef unsigned long long ull;

// ---------------- f32x2 helpers (flash) ----------------
__device__ __forceinline__ ull pk2(float lo, float hi) {
    ull r; asm("mov.b64 %0,{%1,%2};" : "=l"(r) : "f"(lo), "f"(hi)); return r;
}
__device__ __forceinline__ ull dup2(float v) {
    ull r; asm("mov.b64 %0,{%1,%1};" : "=l"(r) : "f"(v)); return r;
}
__device__ __forceinline__ void fma2(ull& d, ull a, ull b) {
    asm("fma.rn.f32x2 %0, %1, %2, %0;" : "+l"(d) : "l"(a), "l"(b));
}
__device__ __forceinline__ ull mul2(ull a, ull b) {
    ull r; asm("mul.rn.f32x2 %0, %1, %2;" : "=l"(r) : "l"(a), "l"(b)); return r;
}
__device__ __forceinline__ float2 upk2(ull v) {
    float2 f; asm("mov.b64 {%0,%1}, %2;" : "=f"(f.x), "=f"(f.y) : "l"(v)); return f;
}

// ---------------- mma / ldmatrix / cp.async helpers (all sm_80 features) ----
__device__ __forceinline__ uint32_t smem_u32(const void* p) {
    uint32_t a;
    asm("{ .reg .u64 t; cvta.to.shared.u64 t, %1; cvt.u32.u64 %0, t; }" : "=r"(a) : "l"(p));
    return a;
}
__device__ __forceinline__ void cpa16(uint32_t s, const void* g) {
    asm volatile("cp.async.cg.shared.global [%0], [%1], 16;" :: "r"(s), "l"(g));
}
#define CP_COMMIT() asm volatile("cp.async.commit_group;" ::: "memory")
#define CP_WAIT(n)  asm volatile("cp.async.wait_group %0;" :: "n"(n) : "memory")
#define LDSM_X4(r0,r1,r2,r3,addr) \
    asm volatile("ldmatrix.sync.aligned.m8n8.x4.shared.b16 {%0,%1,%2,%3}, [%4];" \
                 : "=r"(r0),"=r"(r1),"=r"(r2),"=r"(r3) : "r"(addr))
#define MMA16816(d, a, b) \
    asm volatile("mma.sync.aligned.m16n8k16.row.col.f32.bf16.bf16.f32 " \
                 "{%0,%1,%2,%3},{%4,%5,%6,%7},{%8,%9},{%0,%1,%2,%3};" \
                 : "+f"((d)[0]),"+f"((d)[1]),"+f"((d)[2]),"+f"((d)[3]) \
                 : "r"((a)[0]),"r"((a)[1]),"r"((a)[2]),"r"((a)[3]), \
                   "r"((b)[0]),"r"((b)[1]))

__device__ __forceinline__ uint32_t pkbf2(float a, float b) {
    __nv_bfloat162 h = __floats2bfloat162_rn(a, b);
    return *reinterpret_cast<uint32_t*>(&h);
}

// ---------------- device-global scratch ----------------
__device__ float          g_qkv[(size_t)C_TOK * C_3E];   // stage1 out (fp32)
__device__ __nv_bfloat16  g_x3[(size_t)C_TOK * K3];      // x packed   [ah|ah|al]
__device__ __nv_bfloat16  g_a3[(size_t)C_TOK * K3];      // attn out packed
__device__ __nv_bfloat16  g_wa3[(size_t)C_3E * K3];      // W_attn^T packed [bh|bl|bh]
__device__ __nv_bfloat16  g_wp3[(size_t)C_E * K3];       // W_proj^T packed

// ---------------------------------------------------------------------------
// split-pack x: fp32 [M][1024] -> bf16 [M][3072] = [ah | ah | al]
// ---------------------------------------------------------------------------
__global__ __launch_bounds__(256)
void split_pack_kernel(const float* __restrict__ in, __nv_bfloat16* __restrict__ o3)
{
    const int i4 = blockIdx.x * 256 + threadIdx.x;          // 2M quads
    const int m  = i4 >> 8;              // 1024/4 = 256 quads per row
    const int kq = i4 & 255;
    const float4 v = *(const float4*)(in + (size_t)m * C_E + kq * 4);
    float al0 = v.x - __bfloat162float(__float2bfloat16_rn(v.x));
    float al1 = v.y - __bfloat162float(__float2bfloat16_rn(v.y));
    float al2 = v.z - __bfloat162float(__float2bfloat16_rn(v.z));
    float al3 = v.w - __bfloat162float(__float2bfloat16_rn(v.w));
    uint2 hh = make_uint2(pkbf2(v.x, v.y), pkbf2(v.z, v.w));
    uint2 ll = make_uint2(pkbf2(al0, al1), pkbf2(al2, al3));
    __nv_bfloat16* base = o3 + (size_t)m * K3 + kq * 4;
    *(uint2*)(base)          = hh;
    *(uint2*)(base + C_E)    = hh;
    *(uint2*)(base + 2*C_E)  = ll;
}

// ---------------------------------------------------------------------------
// transpose + split-pack W[K=1024][N] -> Wt3[N][3072] = [bh | bl | bh]
// ---------------------------------------------------------------------------
__global__ __launch_bounds__(256)
void transpose_pack_kernel(const float* __restrict__ W, __nv_bfloat16* __restrict__ T3, int N)
{
    __shared__ float t[32][33];
    const int tx = threadIdx.x, ty = threadIdx.y;
    const int n0 = blockIdx.x * 32, k0 = blockIdx.y * 32;
    #pragma unroll
    for (int i = 0; i < 4; i++)
        t[ty + i * 8][tx] = W[(size_t)(k0 + ty + i * 8) * N + n0 + tx];
    __syncthreads();
    #pragma unroll
    for (int i = 0; i < 4; i++) {
        const float v = t[tx][ty + i * 8];
        const __nv_bfloat16 bh = __float2bfloat16_rn(v);
        const __nv_bfloat16 bl = __float2bfloat16_rn(v - __bfloat162float(bh));
        __nv_bfloat16* base = T3 + (size_t)(n0 + ty + i * 8) * K3 + k0 + tx;
        base[0]       = bh;
        base[C_E]     = bl;
        base[2*C_E]   = bh;
    }
}

// ---------------------------------------------------------------------------
// bf16 HGEMM: C[M,N] = A3[M,K3] @ B3[N,K3]^T + bias[N]   (fp32 accumulate)
// CTA 128x128, 8 warps (64x32 each), K-chunk 32, cp.async double buffer.
// smem layout per tile: row r (64B) of 4x16B chunks, chunk cc stored at
// cc^(r&3) -> conflict-free ldmatrix.x4 for both operands.
// ---------------------------------------------------------------------------
__global__ __launch_bounds__(256)
void hgemm_bf16_kernel(const __nv_bfloat16* __restrict__ A3,
                       const __nv_bfloat16* __restrict__ B3,
                       const float* __restrict__ bias,
                       float* __restrict__ C, int N)
{
    __shared__ __align__(16) __nv_bfloat16 smA[2][128 * 32];
    __shared__ __align__(16) __nv_bfloat16 smB[2][128 * 32];
    __shared__ float bias_s[128];

    const int t    = threadIdx.x;
    const int lane = t & 31;
    const int wid  = t >> 5;
    const int bm   = blockIdx.y * 128;
    const int bn   = blockIdx.x * 128;
    const int wm   = (wid & 1) * 64;
    const int wn   = (wid >> 1) * 32;

    if (t < 128) bias_s[t] = bias[bn + t];

    const uint32_t sa = smem_u32(smA);
    const uint32_t sb = smem_u32(smB);

    // ---- fill mapping: thread -> 2 adjacent 16B chunks of one row (A and B)
    const int fr = t >> 1;                 // row 0..127
    const int fc = (t & 1) * 2;            // first chunk 0 or 2
    const uint32_t so0 = fr * 64u + (uint32_t)(((fc    ) ^ (fr & 3)) << 4);
    const uint32_t so1 = fr * 64u + (uint32_t)(((fc + 1) ^ (fr & 3)) << 4);
    const __nv_bfloat16* gA = A3 + (size_t)(bm + fr) * K3 + fc * 8;
    const __nv_bfloat16* gB = B3 + (size_t)(bn + fr) * K3 + fc * 8;

    // ---- ldmatrix per-lane address precompute
    const int lr = lane & 7;
    const int ccA = (lane >> 4) & 1;       // k-chunk bit for A tiles
    const int ahalf = (lane >> 3) & 1;     // m 8-row half
    const int ccB = (lane >> 3) & 1;       // k-chunk bit for B tiles
    const int bhalf = (lane >> 4) & 1;     // n 8-row half
    uint32_t offA[4]; int rm3A[4];
    #pragma unroll
    for (int i = 0; i < 4; i++) {
        const int r = wm + i * 16 + ahalf * 8 + lr;
        offA[i] = (uint32_t)r * 64u; rm3A[i] = r & 3;
    }
    uint32_t offB[2]; int rm3B[2];
    #pragma unroll
    for (int j = 0; j < 2; j++) {
        const int r = wn + j * 16 + bhalf * 8 + lr;
        offB[j] = (uint32_t)r * 64u; rm3B[j] = r & 3;
    }

    float acc[4][4][4];
    #pragma unroll
    for (int i = 0; i < 4; i++)
        #pragma unroll
        for (int n = 0; n < 4; n++)
            #pragma unroll
            for (int k = 0; k < 4; k++) acc[i][n][k] = 0.f;

    // prologue: chunk 0 -> buf 0
    cpa16(sa + so0, gA);     cpa16(sa + so1, gA + 8);
    cpa16(sb + so0, gB);     cpa16(sb + so1, gB + 8);
    CP_COMMIT();

    for (int c = 0; c < NCH; c++) {
        const int buf = c & 1;
        if (c + 1 < NCH) {
            const uint32_t d = (uint32_t)(buf ^ 1) * 8192u;
            const __nv_bfloat16* ga = gA + (c + 1) * KC;
            const __nv_bfloat16* gb = gB + (c + 1) * KC;
            cpa16(sa + d + so0, ga);     cpa16(sa + d + so1, ga + 8);
            cpa16(sb + d + so0, gb);     cpa16(sb + d + so1, gb + 8);
            CP_COMMIT();
            CP_WAIT(1);
        } else {
            CP_WAIT(0);
        }
        __syncthreads();

        const uint32_t ab = sa + (uint32_t)buf * 8192u;
        const uint32_t bb = sb + (uint32_t)buf * 8192u;
        #pragma unroll
        for (int s = 0; s < 2; s++) {
            uint32_t a[4][4];
            #pragma unroll
            for (int i = 0; i < 4; i++) {
                const uint32_t addr = ab + offA[i] +
                    (uint32_t)((((s << 1) | ccA) ^ rm3A[i]) << 4);
                LDSM_X4(a[i][0], a[i][1], a[i][2], a[i][3], addr);
            }
            uint32_t bfr[4][2];
            #pragma unroll
            for (int j = 0; j < 2; j++) {
                const uint32_t addr = bb + offB[j] +
                    (uint32_t)((((s << 1) | ccB) ^ rm3B[j]) << 4);
                uint32_t r0, r1, r2, r3;
                LDSM_X4(r0, r1, r2, r3, addr);
                bfr[2 * j][0] = r0;     bfr[2 * j][1] = r1;
                bfr[2 * j + 1][0] = r2; bfr[2 * j + 1][1] = r3;
            }
            #pragma unroll
            for (int i = 0; i < 4; i++)
                #pragma unroll
                for (int n = 0; n < 4; n++)
                    MMA16816(acc[i][n], a[i], bfr[n]);
        }
        __syncthreads();
    }

    // epilogue: bias + store fp32
    #pragma unroll
    for (int i = 0; i < 4; i++) {
        #pragma unroll
        for (int n = 0; n < 4; n++) {
            const int lcol = wn + n * 8 + (lane & 3) * 2;
            const int row0 = bm + wm + i * 16 + (lane >> 2);
            const int col  = bn + lcol;
            const float b0 = bias_s[lcol], b1 = bias_s[lcol + 1];
            float2 v0 = make_float2(acc[i][n][0] + b0, acc[i][n][1] + b1);
            float2 v1 = make_float2(acc[i][n][2] + b0, acc[i][n][3] + b1);
            *(float2*)(C + (size_t)row0 * N + col)       = v0;
            *(float2*)(C + (size_t)(row0 + 8) * N + col) = v1;
        }
    }
}

// ---------------------------------------------------------------------------
// Flash attention, fp32, causal (unchanged math). Epilogue emits packed A3
// bf16 [token][3072] = [ah | ah | al] for the stage-3 bf16 GEMM.
// ---------------------------------------------------------------------------
__global__ __launch_bounds__(256, 2)
void flash_attn_kernel(const float* __restrict__ qkv, __nv_bfloat16* __restrict__ a3)
{
    __shared__ float Qt[64 * 64];
    __shared__ float KP[64 * 64];
    __shared__ float Vs[64 * 64];

    const int qt  = (int)gridDim.x - 1 - (int)blockIdx.x;
    const int bh  = blockIdx.y;
    const int b   = bh >> 4;
    const int h   = bh & 15;
    const int tid = threadIdx.x;
    const int tx  = tid & 15;
    const int ty  = tid >> 4;

    const float* Qg = qkv + (size_t)b * C_S * C_3E + h * 64;
    const float* Kg = Qg + C_E;
    const float* Vg = Qg + 2 * C_E;

    #pragma unroll
    for (int it = 0; it < 4; it++) {
        const int lid = it * 256 + tid;
        const int r  = lid & 63;
        const int d4 = lid >> 6;
        const float4 v = *(const float4*)(Qg + (size_t)(qt * 64 + r) * C_3E + d4 * 4);
        Qt[(d4 * 4 + 0) * 64 + r] = v.x;
        Qt[(d4 * 4 + 1) * 64 + r] = v.y;
        Qt[(d4 * 4 + 2) * 64 + r] = v.z;
        Qt[(d4 * 4 + 3) * 64 + r] = v.w;
    }

    const float NEG_INF = __int_as_float(0xff800000);
    float m[4], l[4];
    ull o2[4][2];
    #pragma unroll
    for (int r = 0; r < 4; r++) { m[r] = NEG_INF; l[r] = 0.f; o2[r][0] = 0ull; o2[r][1] = 0ull; }

    for (int kt = 0; kt <= qt; kt++) {
        __syncthreads();
        #pragma unroll
        for (int it = 0; it < 4; it++) {
            const int lid = it * 256 + tid;
            const int c  = lid & 63;
            const int d4 = lid >> 6;
            const float4 v = *(const float4*)(Kg + (size_t)(kt * 64 + c) * C_3E + d4 * 4);
            KP[(d4 * 4 + 0) * 64 + c] = v.x;
            KP[(d4 * 4 + 1) * 64 + c] = v.y;
            KP[(d4 * 4 + 2) * 64 + c] = v.z;
            KP[(d4 * 4 + 3) * 64 + c] = v.w;
        }
        #pragma unroll
        for (int it = 0; it < 4; it++) {
            const int lid = it * 256 + tid;
            const int jr = lid >> 4;
            const int d4 = lid & 15;
            *(float4*)(Vs + jr * 64 + d4 * 4) =
                *(const float4*)(Vg + (size_t)(kt * 64 + jr) * C_3E + d4 * 4);
        }
        __syncthreads();

        ull s2[4][2];
        #pragma unroll
        for (int r = 0; r < 4; r++) { s2[r][0] = 0ull; s2[r][1] = 0ull; }
        #pragma unroll 16
        for (int d = 0; d < 64; d++) {
            const float4 a  = *(const float4*)(Qt + d * 64 + ty * 4);
            const float4 bk = *(const float4*)(KP + d * 64 + tx * 4);
            const ull b01 = pk2(bk.x, bk.y);
            const ull b23 = pk2(bk.z, bk.w);
            const ull a0 = dup2(a.x), a1 = dup2(a.y), a2 = dup2(a.z), a3 = dup2(a.w);
            fma2(s2[0][0], a0, b01); fma2(s2[0][1], a0, b23);
            fma2(s2[1][0], a1, b01); fma2(s2[1][1], a1, b23);
            fma2(s2[2][0], a2, b01); fma2(s2[2][1], a2, b23);
            fma2(s2[3][0], a3, b01); fma2(s2[3][1], a3, b23);
        }

        float p[4][4];
        float alpha[4];
        const bool diag = (kt == qt);
        #pragma unroll
        for (int r = 0; r < 4; r++) {
            const float2 t0 = upk2(s2[r][0]);
            const float2 t1 = upk2(s2[r][1]);
            float sv[4] = { t0.x, t0.y, t1.x, t1.y };
            float mx = NEG_INF;
            #pragma unroll
            for (int c = 0; c < 4; c++) {
                float xv = sv[c] * 0.125f;
                if (diag && (tx * 4 + c > ty * 4 + r)) xv = -1e30f;
                sv[c] = xv;
                mx = fmaxf(mx, xv);
            }
            mx = fmaxf(mx, __shfl_xor_sync(0xffffffffu, mx, 1));
            mx = fmaxf(mx, __shfl_xor_sync(0xffffffffu, mx, 2));
            mx = fmaxf(mx, __shfl_xor_sync(0xffffffffu, mx, 4));
            mx = fmaxf(mx, __shfl_xor_sync(0xffffffffu, mx, 8));
            const float mn = fmaxf(m[r], mx);
            alpha[r] = __expf(m[r] - mn);
            m[r] = mn;
            float ls = 0.f;
            #pragma unroll
            for (int c = 0; c < 4; c++) {
                const float pe = __expf(sv[c] - mn);
                p[r][c] = pe;
                ls += pe;
            }
            ls += __shfl_xor_sync(0xffffffffu, ls, 1);
            ls += __shfl_xor_sync(0xffffffffu, ls, 2);
            ls += __shfl_xor_sync(0xffffffffu, ls, 4);
            ls += __shfl_xor_sync(0xffffffffu, ls, 8);
            l[r] = l[r] * alpha[r] + ls;
        }

        __syncthreads();
        #pragma unroll
        for (int c = 0; c < 4; c++) {
            const float4 pv = make_float4(p[0][c], p[1][c], p[2][c], p[3][c]);
            *(float4*)(KP + (tx * 4 + c) * 64 + ((ty ^ tx) * 4)) = pv;
        }
        __syncthreads();

        #pragma unroll
        for (int r = 0; r < 4; r++) {
            const ull a2 = dup2(alpha[r]);
            o2[r][0] = mul2(o2[r][0], a2);
            o2[r][1] = mul2(o2[r][1], a2);
        }
        #pragma unroll 8
        for (int j = 0; j < 64; j++) {
            const float4 a = *(const float4*)(KP + j * 64 + ((ty ^ (j >> 2)) * 4));
            const float4 v = *(const float4*)(Vs + j * 64 + tx * 4);
            const ull v01 = pk2(v.x, v.y);
            const ull v23 = pk2(v.z, v.w);
            const ull a0 = dup2(a.x), a1 = dup2(a.y), a2r = dup2(a.z), a3 = dup2(a.w);
            fma2(o2[0][0], a0,  v01); fma2(o2[0][1], a0,  v23);
            fma2(o2[1][0], a1,  v01); fma2(o2[1][1], a1,  v23);
            fma2(o2[2][0], a2r, v01); fma2(o2[2][1], a2r, v23);
            fma2(o2[3][0], a3,  v01); fma2(o2[3][1], a3,  v23);
        }
    }

    // epilogue: divide by l, split-pack bf16, store [token, 3K packed]
    const size_t ob = ((size_t)(b * C_S + qt * 64)) * K3 + h * 64;
    #pragma unroll
    for (int r = 0; r < 4; r++) {
        const float inv = 1.0f / l[r];
        const float2 c0 = upk2(o2[r][0]);
        const float2 c1 = upk2(o2[r][1]);
        const float ov0 = c0.x * inv, ov1 = c0.y * inv, ov2 = c1.x * inv, ov3 = c1.y * inv;
        const float al0 = ov0 - __bfloat162float(__float2bfloat16_rn(ov0));
        const float al1 = ov1 - __bfloat162float(__float2bfloat16_rn(ov1));
        const float al2 = ov2 - __bfloat162float(__float2bfloat16_rn(ov2));
        const float al3 = ov3 - __bfloat162float(__float2bfloat16_rn(ov3));
        uint2 hh = make_uint2(pkbf2(ov0, ov1), pkbf2(ov2, ov3));
        uint2 ll = make_uint2(pkbf2(al0, al1), pkbf2(al2, al3));
        __nv_bfloat16* base = a3 + ob + (size_t)(ty * 4 + r) * K3 + tx * 4;
        *(uint2*)(base)         = hh;
        *(uint2*)(base + C_E)   = hh;
        *(uint2*)(base + 2*C_E) = ll;
    }
}

// ---------------------------------------------------------------------------
extern "C" void kernel_launch(void* const* d_in, const int* in_sizes, int n_in,
                              void* d_out, int out_size)
{
    (void)in_sizes; (void)n_in; (void)out_size;
    const float* x  = (const float*)d_in[0];
    const float* Wa = (const float*)d_in[1];
    const float* ba = (const float*)d_in[2];
    const float* Wp = (const float*)d_in[3];
    const float* bp = (const float*)d_in[4];
    float* out = (float*)d_out;

    float* qkv; __nv_bfloat16 *x3, *a3, *wa3, *wp3;
    cudaGetSymbolAddress((void**)&qkv, g_qkv);
    cudaGetSymbolAddress((void**)&x3,  g_x3);
    cudaGetSymbolAddress((void**)&a3,  g_a3);
    cudaGetSymbolAddress((void**)&wa3, g_wa3);
    cudaGetSymbolAddress((void**)&wp3, g_wp3);

    // Stage 0: packing
    split_pack_kernel<<<(C_TOK * C_E / 4) / 256, 256>>>(x, x3);
    transpose_pack_kernel<<<dim3(C_3E / 32, C_E / 32), dim3(32, 8)>>>(Wa, wa3, C_3E);
    transpose_pack_kernel<<<dim3(C_E  / 32, C_E / 32), dim3(32, 8)>>>(Wp, wp3, C_E);

    // Stage 1: QKV = x @ W_attn + b_attn   (bf16 tensor path, 3-term split)
    hgemm_bf16_kernel<<<dim3(C_3E / 128, C_TOK / 128), 256>>>(x3, wa3, ba, qkv, C_3E);

    // Stage 2: causal flash attention -> packed A3
    flash_attn_kernel<<<dim3(C_S / 64, 4 * C_H), 256>>>(qkv, a3);

    // Stage 3: out = attn @ W_proj + b_proj
    hgemm_bf16_kernel<<<dim3(C_E / 128, C_TOK / 128), 256>>>(a3, wp3, bp, out, C_E);
}

// round 6
// speedup vs baseline: 2.0147x; 1.6585x over previous
#include <cuda_runtime.h>
#include <cuda_bf16.h>
#include <cstdint>

// ---------------------------------------------------------------------------
// MultiHeadAttention (B=4, S=2048, E=1024, H=16, hd=64), fp32 in/out.
// All heavy math on legacy tensor path (mma.sync.m16n8k16 bf16) with 3-term
// hi/lo splits for fp32-level accuracy:
//   GEMMs: A3=[ah|ah|al], B3=[bh|bl|bh] packed along K (K'=3072)
//   Flash: S = qh.kh + qh.kl + ql.kh ; O += ph.vh + ph.vl + pl.vh
// ---------------------------------------------------------------------------

#define C_S   2048
#define C_E   1024
#define C_3E  3072
#define C_H   16
#define C_TOK 8192
#define K3    3072
#define KC    32
#define NCH   (K3/KC)   // 96
#define NSTAGE 4

// ---------------- common helpers ----------------
__device__ __forceinline__ uint32_t smem_u32(const void* p) {
    uint32_t a;
    asm("{ .reg .u64 t; cvta.to.shared.u64 t, %1; cvt.u32.u64 %0, t; }" : "=r"(a) : "l"(p));
    return a;
}
__device__ __forceinline__ void cpa16(uint32_t s, const void* g) {
    asm volatile("cp.async.cg.shared.global [%0], [%1], 16;" :: "r"(s), "l"(g));
}
#define CP_COMMIT() asm volatile("cp.async.commit_group;" ::: "memory")
#define CP_WAIT(n)  asm volatile("cp.async.wait_group %0;" :: "n"(n) : "memory")
#define LDSM_X4(r0,r1,r2,r3,addr) \
    asm volatile("ldmatrix.sync.aligned.m8n8.x4.shared.b16 {%0,%1,%2,%3}, [%4];" \
                 : "=r"(r0),"=r"(r1),"=r"(r2),"=r"(r3) : "r"(addr))
#define LDSM_X4T(r0,r1,r2,r3,addr) \
    asm volatile("ldmatrix.sync.aligned.m8n8.x4.trans.shared.b16 {%0,%1,%2,%3}, [%4];" \
                 : "=r"(r0),"=r"(r1),"=r"(r2),"=r"(r3) : "r"(addr))
#define MMA16816(d, a, b) \
    asm volatile("mma.sync.aligned.m16n8k16.row.col.f32.bf16.bf16.f32 " \
                 "{%0,%1,%2,%3},{%4,%5,%6,%7},{%8,%9},{%0,%1,%2,%3};" \
                 : "+f"((d)[0]),"+f"((d)[1]),"+f"((d)[2]),"+f"((d)[3]) \
                 : "r"((a)[0]),"r"((a)[1]),"r"((a)[2]),"r"((a)[3]), \
                   "r"((b)[0]),"r"((b)[1]))

__device__ __forceinline__ uint32_t pkbf2(float a, float b) {
    __nv_bfloat162 h = __floats2bfloat162_rn(a, b);
    return *reinterpret_cast<uint32_t*>(&h);
}
// split pair into bf16 hi pair + lo (residual) pair
__device__ __forceinline__ void bsplit2(float a, float b, uint32_t& hi, uint32_t& lo) {
    const __nv_bfloat16 ah = __float2bfloat16_rn(a);
    const __nv_bfloat16 bh = __float2bfloat16_rn(b);
    __nv_bfloat162 hp; hp.x = ah; hp.y = bh;
    hi = *reinterpret_cast<uint32_t*>(&hp);
    lo = pkbf2(a - __bfloat162float(ah), b - __bfloat162float(bh));
}

// ---------------- device-global scratch ----------------
__device__ float          g_qkv[(size_t)C_TOK * C_3E];
__device__ __nv_bfloat16  g_x3[(size_t)C_TOK * K3];
__device__ __nv_bfloat16  g_a3[(size_t)C_TOK * K3];
__device__ __nv_bfloat16  g_wa3[(size_t)C_3E * K3];
__device__ __nv_bfloat16  g_wp3[(size_t)C_E * K3];

// ---------------------------------------------------------------------------
// split-pack x: fp32 [M][1024] -> bf16 [M][3072] = [ah | ah | al]
// ---------------------------------------------------------------------------
__global__ __launch_bounds__(256)
void split_pack_kernel(const float* __restrict__ in, __nv_bfloat16* __restrict__ o3)
{
    const int i4 = blockIdx.x * 256 + threadIdx.x;
    const int m  = i4 >> 8;
    const int kq = i4 & 255;
    const float4 v = *(const float4*)(in + (size_t)m * C_E + kq * 4);
    uint32_t h0, l0, h1, l1;
    bsplit2(v.x, v.y, h0, l0);
    bsplit2(v.z, v.w, h1, l1);
    uint2 hh = make_uint2(h0, h1);
    uint2 ll = make_uint2(l0, l1);
    __nv_bfloat16* base = o3 + (size_t)m * K3 + kq * 4;
    *(uint2*)(base)          = hh;
    *(uint2*)(base + C_E)    = hh;
    *(uint2*)(base + 2*C_E)  = ll;
}

// ---------------------------------------------------------------------------
// transpose + split-pack W[K=1024][N] -> Wt3[N][3072] = [bh | bl | bh]
// ---------------------------------------------------------------------------
__global__ __launch_bounds__(256)
void transpose_pack_kernel(const float* __restrict__ W, __nv_bfloat16* __restrict__ T3, int N)
{
    __shared__ float t[32][33];
    const int tx = threadIdx.x, ty = threadIdx.y;
    const int n0 = blockIdx.x * 32, k0 = blockIdx.y * 32;
    #pragma unroll
    for (int i = 0; i < 4; i++)
        t[ty + i * 8][tx] = W[(size_t)(k0 + ty + i * 8) * N + n0 + tx];
    __syncthreads();
    #pragma unroll
    for (int i = 0; i < 4; i++) {
        const float v = t[tx][ty + i * 8];
        const __nv_bfloat16 bh = __float2bfloat16_rn(v);
        const __nv_bfloat16 bl = __float2bfloat16_rn(v - __bfloat162float(bh));
        __nv_bfloat16* base = T3 + (size_t)(n0 + ty + i * 8) * K3 + k0 + tx;
        base[0]       = bh;
        base[C_E]     = bl;
        base[2*C_E]   = bh;
    }
}

// ---------------------------------------------------------------------------
// bf16 HGEMM: C = A3 @ B3^T + bias. CTA 128x128, 8 warps (64x32), K-chunk 32,
// 4-stage cp.async pipeline, ONE __syncthreads per chunk.
// smem row = 64B (4x16B chunks), chunk cc stored at cc^(r&3).
// ---------------------------------------------------------------------------
__global__ __launch_bounds__(256)
void hgemm_bf16_kernel(const __nv_bfloat16* __restrict__ A3,
                       const __nv_bfloat16* __restrict__ B3,
                       const float* __restrict__ bias,
                       float* __restrict__ C, int N)
{
    extern __shared__ __align__(16) unsigned char dsm[];
    // A stages: [0, 32KB), B stages: [32KB, 64KB); 8KB per stage each
    __shared__ float bias_s[128];

    const int t    = threadIdx.x;
    const int lane = t & 31;
    const int wid  = t >> 5;
    const int bm   = blockIdx.y * 128;
    const int bn   = blockIdx.x * 128;
    const int wm   = (wid & 1) * 64;
    const int wn   = (wid >> 1) * 32;

    if (t < 128) bias_s[t] = bias[bn + t];

    const uint32_t sa = smem_u32(dsm);
    const uint32_t sb = sa + 32768u;

    const int fr = t >> 1;
    const int fc = (t & 1) * 2;
    const uint32_t so0 = fr * 64u + (uint32_t)(((fc    ) ^ (fr & 3)) << 4);
    const uint32_t so1 = fr * 64u + (uint32_t)(((fc + 1) ^ (fr & 3)) << 4);
    const __nv_bfloat16* gA = A3 + (size_t)(bm + fr) * K3 + fc * 8;
    const __nv_bfloat16* gB = B3 + (size_t)(bn + fr) * K3 + fc * 8;

    const int lr = lane & 7;
    const int ccA = (lane >> 4) & 1;
    const int ahalf = (lane >> 3) & 1;
    const int ccB = (lane >> 3) & 1;
    const int bhalf = (lane >> 4) & 1;
    uint32_t offA[4]; int rm3A[4];
    #pragma unroll
    for (int i = 0; i < 4; i++) {
        const int r = wm + i * 16 + ahalf * 8 + lr;
        offA[i] = (uint32_t)r * 64u; rm3A[i] = r & 3;
    }
    uint32_t offB[2]; int rm3B[2];
    #pragma unroll
    for (int j = 0; j < 2; j++) {
        const int r = wn + j * 16 + bhalf * 8 + lr;
        offB[j] = (uint32_t)r * 64u; rm3B[j] = r & 3;
    }

    float acc[4][4][4];
    #pragma unroll
    for (int i = 0; i < 4; i++)
        #pragma unroll
        for (int n = 0; n < 4; n++)
            #pragma unroll
            for (int k = 0; k < 4; k++) acc[i][n][k] = 0.f;

    // prologue: stages 0..2
    #pragma unroll
    for (int p = 0; p < NSTAGE - 1; p++) {
        const uint32_t d = (uint32_t)p * 8192u;
        const __nv_bfloat16* ga = gA + p * KC;
        const __nv_bfloat16* gb = gB + p * KC;
        cpa16(sa + d + so0, ga);     cpa16(sa + d + so1, ga + 8);
        cpa16(sb + d + so0, gb);     cpa16(sb + d + so1, gb + 8);
        CP_COMMIT();
    }

    for (int c = 0; c < NCH; c++) {
        CP_WAIT(NSTAGE - 2);
        __syncthreads();
        if (c + NSTAGE - 1 < NCH) {
            const uint32_t d = (uint32_t)((c + NSTAGE - 1) & (NSTAGE - 1)) * 8192u;
            const __nv_bfloat16* ga = gA + (c + NSTAGE - 1) * KC;
            const __nv_bfloat16* gb = gB + (c + NSTAGE - 1) * KC;
            cpa16(sa + d + so0, ga);     cpa16(sa + d + so1, ga + 8);
            cpa16(sb + d + so0, gb);     cpa16(sb + d + so1, gb + 8);
        }
        CP_COMMIT();   // empty group in tail keeps wait_group accounting exact

        const uint32_t ab = sa + (uint32_t)(c & (NSTAGE - 1)) * 8192u;
        const uint32_t bb = sb + (uint32_t)(c & (NSTAGE - 1)) * 8192u;
        #pragma unroll
        for (int s = 0; s < 2; s++) {
            uint32_t a[4][4];
            #pragma unroll
            for (int i = 0; i < 4; i++) {
                const uint32_t addr = ab + offA[i] +
                    (uint32_t)((((s << 1) | ccA) ^ rm3A[i]) << 4);
                LDSM_X4(a[i][0], a[i][1], a[i][2], a[i][3], addr);
            }
            uint32_t bfr[4][2];
            #pragma unroll
            for (int j = 0; j < 2; j++) {
                const uint32_t addr = bb + offB[j] +
                    (uint32_t)((((s << 1) | ccB) ^ rm3B[j]) << 4);
                uint32_t r0, r1, r2, r3;
                LDSM_X4(r0, r1, r2, r3, addr);
                bfr[2 * j][0] = r0;     bfr[2 * j][1] = r1;
                bfr[2 * j + 1][0] = r2; bfr[2 * j + 1][1] = r3;
            }
            #pragma unroll
            for (int i = 0; i < 4; i++)
                #pragma unroll
                for (int n = 0; n < 4; n++)
                    MMA16816(acc[i][n], a[i], bfr[n]);
        }
    }

    __syncthreads();
    #pragma unroll
    for (int i = 0; i < 4; i++) {
        #pragma unroll
        for (int n = 0; n < 4; n++) {
            const int lcol = wn + n * 8 + (lane & 3) * 2;
            const int row0 = bm + wm + i * 16 + (lane >> 2);
            const int col  = bn + lcol;
            const float b0 = bias_s[lcol], b1 = bias_s[lcol + 1];
            float2 v0 = make_float2(acc[i][n][0] + b0, acc[i][n][1] + b1);
            float2 v1 = make_float2(acc[i][n][2] + b0, acc[i][n][3] + b1);
            *(float2*)(C + (size_t)row0 * N + col)       = v0;
            *(float2*)(C + (size_t)(row0 + 8) * N + col) = v1;
        }
    }
}

// ---------------------------------------------------------------------------
// Flash attention on tensor cores (FA2-style). Block = 128 thr (4 warps),
// each warp owns 16 q-rows of a 64-row q-tile. hi/lo bf16 splits everywhere.
// K is B-operand directly ([j][d] rows); V via ldmatrix.trans; P stays in regs.
// smem rows = 128B (8 chunks), chunk cc stored at cc^(r&7).
// ---------------------------------------------------------------------------
__global__ __launch_bounds__(128, 3)
void flash_mma_kernel(const float* __restrict__ qkv, __nv_bfloat16* __restrict__ a3)
{
    __shared__ __align__(16) __nv_bfloat16 sQh[64 * 64], sQl[64 * 64];
    __shared__ __align__(16) __nv_bfloat16 sKh[64 * 64], sKl[64 * 64];
    __shared__ __align__(16) __nv_bfloat16 sVh[64 * 64], sVl[64 * 64];

    const int qt  = (int)gridDim.x - 1 - (int)blockIdx.x;
    const int bh  = blockIdx.y;
    const int b   = bh >> 4;
    const int h   = bh & 15;
    const int tid = threadIdx.x;
    const int lane = tid & 31;
    const int wq   = tid >> 5;           // warp q-row block: rows wq*16..+15

    const float* Qg = qkv + (size_t)b * C_S * C_3E + h * 64;
    const float* Kg = Qg + C_E;
    const float* Vg = Qg + 2 * C_E;

    const uint32_t bQh = smem_u32(sQh), bQl = smem_u32(sQl);
    const uint32_t bKh = smem_u32(sKh), bKl = smem_u32(sKl);
    const uint32_t bVh = smem_u32(sVh), bVl = smem_u32(sVl);

    // ---- load Q tile, split to hi/lo smem (64 rows x 8 chunks of 16B)
    #pragma unroll
    for (int it = 0; it < 4; it++) {
        const int ch = it * 128 + tid;
        const int r  = ch >> 3;
        const int cc = ch & 7;
        const float* src = Qg + (size_t)(qt * 64 + r) * C_3E + cc * 8;
        const float4 u = *(const float4*)src;
        const float4 w = *(const float4*)(src + 4);
        uint4 hi, lo;
        bsplit2(u.x, u.y, hi.x, lo.x);
        bsplit2(u.z, u.w, hi.y, lo.y);
        bsplit2(w.x, w.y, hi.z, lo.z);
        bsplit2(w.z, w.w, hi.w, lo.w);
        const uint32_t off = r * 128u + (uint32_t)((cc ^ (r & 7)) << 4);
        *(uint4*)((char*)sQh + off) = hi;
        *(uint4*)((char*)sQl + off) = lo;
    }
    __syncthreads();

    // ---- build Q A-fragments in registers (persist whole kernel)
    uint32_t qhf[4][4], qlf[4][4];
    {
        const int arow = wq * 16 + ((lane >> 3) & 1) * 8 + (lane & 7);
        const uint32_t ro = (uint32_t)arow * 128u;
        const int rm = arow & 7;
        const int cca = (lane >> 4) & 1;
        #pragma unroll
        for (int ks = 0; ks < 4; ks++) {
            const uint32_t co = (uint32_t)(((ks * 2 + cca) ^ rm) << 4);
            LDSM_X4(qhf[ks][0], qhf[ks][1], qhf[ks][2], qhf[ks][3], bQh + ro + co);
            LDSM_X4(qlf[ks][0], qlf[ks][1], qlf[ks][2], qlf[ks][3], bQl + ro + co);
        }
    }

    const int g  = lane >> 2;
    const int qq = lane & 3;
    float m0 = -1e30f, m1 = -1e30f, l0 = 0.f, l1 = 0.f;
    float O[8][4];
    #pragma unroll
    for (int dt = 0; dt < 8; dt++)
        #pragma unroll
        for (int k = 0; k < 4; k++) O[dt][k] = 0.f;

    for (int kt = 0; kt <= qt; kt++) {
        __syncthreads();   // prior iteration's ldmatrix reads of K/V done
        // ---- load K and V tiles, split to hi/lo smem
        #pragma unroll
        for (int it = 0; it < 4; it++) {
            const int ch = it * 128 + tid;
            const int r  = ch >> 3;
            const int cc = ch & 7;
            const uint32_t off = r * 128u + (uint32_t)((cc ^ (r & 7)) << 4);
            {
                const float* src = Kg + (size_t)(kt * 64 + r) * C_3E + cc * 8;
                const float4 u = *(const float4*)src;
                const float4 w = *(const float4*)(src + 4);
                uint4 hi, lo;
                bsplit2(u.x, u.y, hi.x, lo.x);
                bsplit2(u.z, u.w, hi.y, lo.y);
                bsplit2(w.x, w.y, hi.z, lo.z);
                bsplit2(w.z, w.w, hi.w, lo.w);
                *(uint4*)((char*)sKh + off) = hi;
                *(uint4*)((char*)sKl + off) = lo;
            }
            {
                const float* src = Vg + (size_t)(kt * 64 + r) * C_3E + cc * 8;
                const float4 u = *(const float4*)src;
                const float4 w = *(const float4*)(src + 4);
                uint4 hi, lo;
                bsplit2(u.x, u.y, hi.x, lo.x);
                bsplit2(u.z, u.w, hi.y, lo.y);
                bsplit2(w.x, w.y, hi.z, lo.z);
                bsplit2(w.z, w.w, hi.w, lo.w);
                *(uint4*)((char*)sVh + off) = hi;
                *(uint4*)((char*)sVl + off) = lo;
            }
        }
        __syncthreads();

        // ---- S = Q.K^T  (3 passes: qh.kh, qh.kl, ql.kh)
        float S[8][4];
        #pragma unroll
        for (int nt = 0; nt < 8; nt++)
            #pragma unroll
            for (int k = 0; k < 4; k++) S[nt][k] = 0.f;

        const int brow_h = ((lane >> 4) & 1) * 8 + (lane & 7);   // within n-tile pair
        const int ccb    = (lane >> 3) & 1;
        #pragma unroll
        for (int pass = 0; pass < 3; pass++) {
            const uint32_t kb = (pass == 1) ? bKl : bKh;
            uint32_t (*af)[4] = (pass == 2) ? qlf : qhf;
            #pragma unroll
            for (int ks = 0; ks < 4; ks++) {
                #pragma unroll
                for (int tp = 0; tp < 4; tp++) {
                    const int brow = tp * 16 + brow_h;
                    const uint32_t addr = kb + (uint32_t)brow * 128u +
                        (uint32_t)((((ks * 2 + ccb)) ^ (brow & 7)) << 4);
                    uint32_t r0, r1, r2, r3;
                    LDSM_X4(r0, r1, r2, r3, addr);
                    uint32_t b0[2] = { r0, r1 };
                    uint32_t b1[2] = { r2, r3 };
                    MMA16816(S[2 * tp],     af[ks], b0);
                    MMA16816(S[2 * tp + 1], af[ks], b1);
                }
            }
        }

        // ---- masked online softmax on fragments
        const bool diag = (kt == qt);
        const int r0l = wq * 16 + g;
        const int r1l = r0l + 8;
        float pv[8][4];
        float mx0 = -1e30f, mx1 = -1e30f;
        #pragma unroll
        for (int t = 0; t < 8; t++) {
            const int c0 = t * 8 + qq * 2;
            float s0 = S[t][0] * 0.125f;
            float s1 = S[t][1] * 0.125f;
            float s2 = S[t][2] * 0.125f;
            float s3 = S[t][3] * 0.125f;
            if (diag) {
                if (c0     > r0l) s0 = -1e30f;
                if (c0 + 1 > r0l) s1 = -1e30f;
                if (c0     > r1l) s2 = -1e30f;
                if (c0 + 1 > r1l) s3 = -1e30f;
            }
            pv[t][0] = s0; pv[t][1] = s1; pv[t][2] = s2; pv[t][3] = s3;
            mx0 = fmaxf(mx0, fmaxf(s0, s1));
            mx1 = fmaxf(mx1, fmaxf(s2, s3));
        }
        mx0 = fmaxf(mx0, __shfl_xor_sync(0xffffffffu, mx0, 1));
        mx0 = fmaxf(mx0, __shfl_xor_sync(0xffffffffu, mx0, 2));
        mx1 = fmaxf(mx1, __shfl_xor_sync(0xffffffffu, mx1, 1));
        mx1 = fmaxf(mx1, __shfl_xor_sync(0xffffffffu, mx1, 2));
        const float mn0 = fmaxf(m0, mx0);
        const float mn1 = fmaxf(m1, mx1);
        const float al0 = __expf(m0 - mn0);
        const float al1 = __expf(m1 - mn1);
        m0 = mn0; m1 = mn1;
        float sum0 = 0.f, sum1 = 0.f;
        #pragma unroll
        for (int t = 0; t < 8; t++) {
            const float p0 = __expf(pv[t][0] - mn0);
            const float p1 = __expf(pv[t][1] - mn0);
            const float p2 = __expf(pv[t][2] - mn1);
            const float p3 = __expf(pv[t][3] - mn1);
            pv[t][0] = p0; pv[t][1] = p1; pv[t][2] = p2; pv[t][3] = p3;
            sum0 += p0 + p1;
            sum1 += p2 + p3;
        }
        sum0 += __shfl_xor_sync(0xffffffffu, sum0, 1);
        sum0 += __shfl_xor_sync(0xffffffffu, sum0, 2);
        sum1 += __shfl_xor_sync(0xffffffffu, sum1, 1);
        sum1 += __shfl_xor_sync(0xffffffffu, sum1, 2);
        l0 = l0 * al0 + sum0;
        l1 = l1 * al1 + sum1;

        // ---- P fragments (acc layout == A-operand layout; hi/lo split)
        uint32_t pha[4][4], pla[4][4];
        #pragma unroll
        for (int s = 0; s < 4; s++) {
            bsplit2(pv[2 * s][0],     pv[2 * s][1],     pha[s][0], pla[s][0]);
            bsplit2(pv[2 * s][2],     pv[2 * s][3],     pha[s][1], pla[s][1]);
            bsplit2(pv[2 * s + 1][0], pv[2 * s + 1][1], pha[s][2], pla[s][2]);
            bsplit2(pv[2 * s + 1][2], pv[2 * s + 1][3], pha[s][3], pla[s][3]);
        }

        // ---- rescale O by alpha
        #pragma unroll
        for (int dt = 0; dt < 8; dt++) {
            O[dt][0] *= al0; O[dt][1] *= al0;
            O[dt][2] *= al1; O[dt][3] *= al1;
        }

        // ---- O += P.V  (passes: ph.vh, pl.vh, ph.vl)
        const int jrow_h = ((lane >> 3) & 1) * 8 + (lane & 7);
        const int dccb   = (lane >> 4) & 1;
        #pragma unroll
        for (int s = 0; s < 4; s++) {
            const int jrow = s * 16 + jrow_h;
            const uint32_t rbase = (uint32_t)jrow * 128u;
            const int rm = jrow & 7;
            uint32_t bv[8][2];
            #pragma unroll
            for (int tp = 0; tp < 4; tp++) {
                const uint32_t addr = bVh + rbase +
                    (uint32_t)(((tp * 2 + dccb) ^ rm) << 4);
                uint32_t r0, r1, r2, r3;
                LDSM_X4T(r0, r1, r2, r3, addr);
                bv[2 * tp][0] = r0;     bv[2 * tp][1] = r1;
                bv[2 * tp + 1][0] = r2; bv[2 * tp + 1][1] = r3;
            }
            #pragma unroll
            for (int dt = 0; dt < 8; dt++) {
                MMA16816(O[dt], pha[s], bv[dt]);
                MMA16816(O[dt], pla[s], bv[dt]);
            }
            #pragma unroll
            for (int tp = 0; tp < 4; tp++) {
                const uint32_t addr = bVl + rbase +
                    (uint32_t)(((tp * 2 + dccb) ^ rm) << 4);
                uint32_t r0, r1, r2, r3;
                LDSM_X4T(r0, r1, r2, r3, addr);
                bv[2 * tp][0] = r0;     bv[2 * tp][1] = r1;
                bv[2 * tp + 1][0] = r2; bv[2 * tp + 1][1] = r3;
            }
            #pragma unroll
            for (int dt = 0; dt < 8; dt++)
                MMA16816(O[dt], pha[s], bv[dt]);
        }
    }

    // ---- epilogue: O /= l, split-pack bf16 -> a3 [ah|ah|al]
    const float inv0 = 1.0f / l0;
    const float inv1 = 1.0f / l1;
    const size_t tok0 = (size_t)(b * C_S + qt * 64 + wq * 16 + g);
    const size_t tok1 = tok0 + 8;
    #pragma unroll
    for (int t = 0; t < 8; t++) {
        const int col = h * 64 + t * 8 + qq * 2;
        uint32_t hi, lo;
        bsplit2(O[t][0] * inv0, O[t][1] * inv0, hi, lo);
        __nv_bfloat16* p0 = a3 + tok0 * K3 + col;
        *(uint32_t*)(p0)          = hi;
        *(uint32_t*)(p0 + C_E)    = hi;
        *(uint32_t*)(p0 + 2*C_E)  = lo;
        bsplit2(O[t][2] * inv1, O[t][3] * inv1, hi, lo);
        __nv_bfloat16* p1 = a3 + tok1 * K3 + col;
        *(uint32_t*)(p1)          = hi;
        *(uint32_t*)(p1 + C_E)    = hi;
        *(uint32_t*)(p1 + 2*C_E)  = lo;
    }
}

// ---------------------------------------------------------------------------
extern "C" void kernel_launch(void* const* d_in, const int* in_sizes, int n_in,
                              void* d_out, int out_size)
{
    (void)in_sizes; (void)n_in; (void)out_size;
    const float* x  = (const float*)d_in[0];
    const float* Wa = (const float*)d_in[1];
    const float* ba = (const float*)d_in[2];
    const float* Wp = (const float*)d_in[3];
    const float* bp = (const float*)d_in[4];
    float* out = (float*)d_out;

    float* qkv; __nv_bfloat16 *x3, *a3, *wa3, *wp3;
    cudaGetSymbolAddress((void**)&qkv, g_qkv);
    cudaGetSymbolAddress((void**)&x3,  g_x3);
    cudaGetSymbolAddress((void**)&a3,  g_a3);
    cudaGetSymbolAddress((void**)&wa3, g_wa3);
    cudaGetSymbolAddress((void**)&wp3, g_wp3);

    cudaFuncSetAttribute(hgemm_bf16_kernel,
                         cudaFuncAttributeMaxDynamicSharedMemorySize, 65536);

    // Stage 0: packing
    split_pack_kernel<<<(C_TOK * C_E / 4) / 256, 256>>>(x, x3);
    transpose_pack_kernel<<<dim3(C_3E / 32, C_E / 32), dim3(32, 8)>>>(Wa, wa3, C_3E);
    transpose_pack_kernel<<<dim3(C_E  / 32, C_E / 32), dim3(32, 8)>>>(Wp, wp3, C_E);

    // Stage 1: QKV projection
    hgemm_bf16_kernel<<<dim3(C_3E / 128, C_TOK / 128), 256, 65536>>>(x3, wa3, ba, qkv, C_3E);

    // Stage 2: causal flash attention (tensor cores) -> packed A3
    flash_mma_kernel<<<dim3(C_S / 64, 4 * C_H), 128>>>(qkv, a3);

    // Stage 3: output projection
    hgemm_bf16_kernel<<<dim3(C_E / 128, C_TOK / 128), 256, 65536>>>(a3, wp3, bp, out, C_E);
}